// round 13
// baseline (speedup 1.0000x reference)
#include <cuda_runtime.h>
#include <cuda_bf16.h>
#include <math.h>
#include <stdint.h>

// Problem constants
#define BB    64
#define CC    512
#define NN    1024          // 32*32 spatial
#define OO    25            // 1 conf + 20 cls + 4 box
#define NCLS  20
#define CONF_T 0.01f
#define NMS_T  0.5f
#define EPS_IOU 1e-28f
#define INV_SCALE 0.0009765625f   // 1/1024
#define MAXC  128
#define FULLM 0xffffffffu

typedef unsigned long long u64;
typedef unsigned short u16;

// Scratch (allocation-free __device__ globals)
__device__ int    g_cnt [BB*NCLS];
__device__ float4 g_cbox[BB*NCLS*MAXC];
__device__ u64    g_ckey[BB*NCLS*MAXC];
__device__ u16    g_wsplit[3*32*512];     // bf16 planes of W: [p][n][k], rows 25-31 zero

__device__ __forceinline__ float sigm(float x) { return 1.0f / (1.0f + expf(-x)); }

// ---------------------------------------------------------------------------
// Exact fp32 -> 3x bf16 decomposition.
// A-side (fast, bit ops): a1 = RN(x), a2 = trunc(r1), a3 = trunc(r2); r3 == 0.
// ---------------------------------------------------------------------------
__device__ __forceinline__ void split3_fast(float x, uint32_t& h1, uint32_t& h2, uint32_t& h3) {
    uint32_t u  = __float_as_uint(x);
    uint32_t t1 = (u + 0x7fffu + ((u >> 16) & 1u)) & 0xffff0000u;  // RN-even bf16
    float    r1 = x - __uint_as_float(t1);
    uint32_t t2 = __float_as_uint(r1) & 0xffff0000u;               // trunc bf16
    float    r2 = r1 - __uint_as_float(t2);
    h1 = t1 >> 16;
    h2 = t2 >> 16;
    h3 = __float_as_uint(r2) >> 16;                                 // exact (<=8 sig bits left)
}

// B-side (precompute kernel, full RN chain)
__device__ __forceinline__ void split3_rn(float x, u16& h1, u16& h2, u16& h3) {
    __nv_bfloat16 v1 = __float2bfloat16_rn(x);
    float r1 = x - __bfloat162float(v1);
    __nv_bfloat16 v2 = __float2bfloat16_rn(r1);
    float r2 = r1 - __bfloat162float(v2);
    __nv_bfloat16 v3 = __float2bfloat16_rn(r2);
    h1 = __bfloat16_as_ushort(v1);
    h2 = __bfloat16_as_ushort(v2);
    h3 = __bfloat16_as_ushort(v3);
}

// m16n8k16 row.col f32.bf16.bf16.f32 (sm_80+ PTX; valid on plain sm_100)
__device__ __forceinline__ void mma16816(float* d, const uint32_t* a, const uint32_t* b) {
    asm volatile(
        "mma.sync.aligned.m16n8k16.row.col.f32.bf16.bf16.f32 "
        "{%0,%1,%2,%3}, {%4,%5,%6,%7}, {%8,%9}, {%0,%1,%2,%3};\n"
        : "+f"(d[0]), "+f"(d[1]), "+f"(d[2]), "+f"(d[3])
        : "r"(a[0]), "r"(a[1]), "r"(a[2]), "r"(a[3]), "r"(b[0]), "r"(b[1]));
}

// ---------------------------------------------------------------------------
// Decode one pixel given its 25 raw logits (bias added here). Same as R10.
// ---------------------------------------------------------------------------
__device__ __forceinline__ void decode_write(int b, int n, const float* acc,
                                             const float* b_s, float* __restrict__ out)
{
    float p[OO];
    #pragma unroll
    for (int o = 0; o < OO; o++) p[o] = acc[o] + b_s[o];

    float conf = sigm(p[0]);

    float m = p[1]; int am = 0;
    #pragma unroll
    for (int k = 1; k < NCLS; k++)
        if (p[1 + k] > m) { m = p[1 + k]; am = k; }

    float s = 0.0f;
    #pragma unroll
    for (int k = 0; k < NCLS; k++) s += expf(p[1 + k] - m);
    float score = conf / s;

    float gx = (float)(n & 31), gy = (float)(n >> 5);
    float cx = (sigm(p[21]) + gx) * 32.0f;
    float cy = (sigm(p[22]) + gy) * 32.0f;
    float w  = expf(p[23]);
    float h  = expf(p[24]);
    float hw = __fmul_rn(w, 0.5f);
    float hh = __fmul_rn(h, 0.5f);
    float x1 = fminf(fmaxf(__fmul_rn(cx - hw, INV_SCALE), 0.0f), 1.0f);
    float y1 = fminf(fmaxf(__fmul_rn(cy - hh, INV_SCALE), 0.0f), 1.0f);
    float x2 = fminf(fmaxf(__fmul_rn(cx + hw, INV_SCALE), 0.0f), 1.0f);
    float y2 = fminf(fmaxf(__fmul_rn(cy + hh, INV_SCALE), 0.0f), 1.0f);

    int i = b * NN + n;
    ((float4*)out)[i] = make_float4(x1, y1, x2, y2);
    out[BB*NN*4 + i] = score;
    out[BB*NN*5 + i] = (float)am;
    out[BB*NN*6 + i] = 0.0f;

    if (score > CONF_T) {
        int idx  = b * NCLS + am;
        int slot = atomicAdd(&g_cnt[idx], 1);
        if (slot < MAXC) {
            float off = __fmul_rn(2.0f, (float)am);
            g_cbox[idx * MAXC + slot] =
                make_float4(x1 + off, y1 + off, x2 + off, y2 + off);
            g_ckey[idx * MAXC + slot] =
                ((u64)__float_as_uint(score) << 32) | (u64)(NN - 1 - n);
        }
    }
}

// ---------------------------------------------------------------------------
// Precompute: W (25x512, rows 25-31 zero) -> 3 exact bf16 planes [p][n][k].
// ---------------------------------------------------------------------------
__global__ void k_wsplit(const float* __restrict__ w_pred)
{
    int n = blockIdx.x;           // 0..31
    int k = threadIdx.x;          // 0..511
    float v = (n < OO) ? w_pred[n * CC + k] : 0.0f;
    u16 h1, h2, h3;
    split3_rn(v, h1, h2, h3);
    g_wsplit[0*32*512 + n*512 + k] = h1;
    g_wsplit[1*32*512 + n*512 + k] = h2;
    g_wsplit[2*32*512 + n*512 + k] = h3;
}

// ---------------------------------------------------------------------------
// Tensor-core GEMM via mma.sync (6-pass exact-split bf16) + decode.
// 1024 CTAs x 128 thr (4 warps). CTA = 64 pixels; warp = 16 pixels.
// K processed in 16 chunks of 32 (2 ksteps of k16).
// smem rows padded to 36 halves (72B) -> conflict-free fragment LDS.
// ---------------------------------------------------------------------------
#define ST      36                 // halves per padded row
#define APL     (64 * ST)          // A plane: 2304 halves = 4608 B
#define BPL     (32 * ST)          // B plane: 1152 halves = 2304 B
#define SMB_B   (3 * APL * 2)      // 13824: B planes base (bytes)
#define SMB_BS  (SMB_B + 3 * BPL * 2)   // 20736: bias base
#define SMEM_SZ (SMB_BS + 128)

__global__ __launch_bounds__(128)
void k_gemm_mma(const float* __restrict__ feat,
                const float* __restrict__ b_pred,
                float* __restrict__ out)
{
    __shared__ __align__(16) char smem[SMEM_SZ];
    u16*   sA  = (u16*)smem;                 // 3 planes of A [p][m][k]
    u16*   sB  = (u16*)(smem + SMB_B);       // 3 planes of B [p][n][k]
    float* b_s = (float*)(smem + SMB_BS);

    const int tid  = threadIdx.x;
    const int wid  = tid >> 5;
    const int lane = tid & 31;
    const int g    = lane >> 2;              // groupID
    const int tig  = lane & 3;               // thread-in-group

    const int gm = blockIdx.x << 6;          // 64 pixels per CTA
    const int b  = gm >> 10;
    const int nb = gm & (NN - 1);

    if (tid < OO) b_s[tid] = b_pred[tid];

    float dacc[4][4];                        // [ntile][c0..c3]
    #pragma unroll
    for (int nt = 0; nt < 4; nt++)
        #pragma unroll
        for (int r = 0; r < 4; r++) dacc[nt][r] = 0.0f;

    const int r0 = wid * 16 + g;             // this thread's A rows
    const int r1 = r0 + 8;
    const float* fb = feat + (size_t)b * CC * NN + nb;
    const uint32_t* wsrc = (const uint32_t*)g_wsplit;

    for (int kc = 0; kc < 16; kc++) {
        __syncthreads();                     // protect prev chunk readers

        // Stage B chunk: 3 planes x 32n x 16 words; 1536 words / 128 thr = 12
        #pragma unroll
        for (int i = 0; i < 12; i++) {
            int idx = i * 128 + tid;
            int p   = idx >> 9;
            int rem = idx & 511;
            int n   = rem >> 4;
            int kw  = rem & 15;
            ((uint32_t*)(smem + SMB_B))[0] = ((uint32_t*)(smem + SMB_B))[0]; // no-op guard
            *(uint32_t*)((u16*)(smem + SMB_B) + p * BPL + n * ST + kw * 2) =
                wsrc[p * 8192 + n * 256 + kc * 16 + kw];
        }

        // Stage A chunk: 32k x 64m fp32 -> exact 3x bf16; 2048 elems / 128 = 16
        #pragma unroll
        for (int i = 0; i < 16; i++) {
            int idx = i * 128 + tid;
            int k   = idx >> 6;
            int m   = idx & 63;
            float x = fb[(size_t)(kc * 32 + k) * NN + m];
            uint32_t h1, h2, h3;
            split3_fast(x, h1, h2, h3);
            int off = m * ST + k;
            sA[0 * APL + off] = (u16)h1;
            sA[1 * APL + off] = (u16)h2;
            sA[2 * APL + off] = (u16)h3;
        }
        __syncthreads();

        // Compute: 2 ksteps of k16
        #pragma unroll
        for (int ks = 0; ks < 2; ks++) {
            const int c0 = ks * 16 + 2 * tig;
            const int c1 = c0 + 8;

            uint32_t a[3][4];
            #pragma unroll
            for (int p = 0; p < 3; p++) {
                const u16* ap = sA + p * APL;
                a[p][0] = *(const uint32_t*)(ap + r0 * ST + c0);
                a[p][1] = *(const uint32_t*)(ap + r1 * ST + c0);
                a[p][2] = *(const uint32_t*)(ap + r0 * ST + c1);
                a[p][3] = *(const uint32_t*)(ap + r1 * ST + c1);
            }

            #pragma unroll
            for (int nt = 0; nt < 4; nt++) {
                const int nr = nt * 8 + g;
                uint32_t bf[3][2];
                #pragma unroll
                for (int p = 0; p < 3; p++) {
                    const u16* bp = sB + p * BPL;
                    bf[p][0] = *(const uint32_t*)(bp + nr * ST + c0);
                    bf[p][1] = *(const uint32_t*)(bp + nr * ST + c1);
                }
                // 6 passes: A1B1, A1B2, A2B1, A2B2, A1B3, A3B1
                mma16816(dacc[nt], a[0], bf[0]);
                mma16816(dacc[nt], a[0], bf[1]);
                mma16816(dacc[nt], a[1], bf[0]);
                mma16816(dacc[nt], a[1], bf[1]);
                mma16816(dacc[nt], a[0], bf[2]);
                mma16816(dacc[nt], a[2], bf[0]);
            }
        }
    }

    // Epilogue: D frags -> smem [64][33] f32 (reuses A region), then decode.
    __syncthreads();
    float* Dt = (float*)smem;
    #pragma unroll
    for (int nt = 0; nt < 4; nt++) {
        int cb = nt * 8 + 2 * tig;
        Dt[r0 * 33 + cb]     = dacc[nt][0];
        Dt[r0 * 33 + cb + 1] = dacc[nt][1];
        Dt[r1 * 33 + cb]     = dacc[nt][2];
        Dt[r1 * 33 + cb + 1] = dacc[nt][3];
    }
    __syncthreads();

    if (tid < 64) {
        float acc[OO];
        #pragma unroll
        for (int o = 0; o < OO; o++) acc[o] = Dt[tid * 33 + o];
        decode_write(b, nb + tid, acc, b_s, out);
    }
}

// ---------------------------------------------------------------------------
// NMS: identical to R10 (measured 34.1us).
// ---------------------------------------------------------------------------
__global__ __launch_bounds__(128)
void k_nms(float* __restrict__ out)
{
    const int b    = blockIdx.x;
    const int c    = blockIdx.y;
    const int idx  = b * NCLS + c;
    const int tid  = threadIdx.x;
    const int warp = tid >> 5;
    const int lane = tid & 31;

    __shared__ int    s_cnt;
    __shared__ u64    tkey[MAXC];
    __shared__ float4 tbox[MAXC];
    __shared__ float4 sbox[MAXC];
    __shared__ float  sarea[MAXC];
    __shared__ short  ssn[MAXC];
    __shared__ uint4  rows[MAXC];

    u64    k0 = g_ckey[idx * MAXC + tid];
    float4 b0 = g_cbox[idx * MAXC + tid];
    if (tid == 0) { int ct = g_cnt[idx]; g_cnt[idx] = 0; s_cnt = min(ct, MAXC); }
    tkey[tid] = k0;
    tbox[tid] = b0;
    __syncthreads();

    const int cnt = s_cnt;
    if (cnt == 0) return;

    if (tid < cnt) {
        u64 ki = tkey[tid];
        int rank = 0;
        for (int j = 0; j < cnt; j++) rank += (tkey[j] > ki);
        float4 bx = tbox[tid];
        sbox[rank]  = bx;
        sarea[rank] = __fmul_rn(bx.z - bx.x, bx.w - bx.y);
        ssn[rank]   = (short)(NN - 1 - (int)(ki & 0xffffffffu));
    }
    __syncthreads();

    const int nch = (cnt + 31) >> 5;
    for (int i = warp; i < cnt; i += 4) {
        float4 kb = sbox[i];
        float  ka = sarea[i];
        unsigned w0 = 0, w1 = 0, w2 = 0, w3 = 0;
        for (int chn = 0; chn < nch; chn++) {
            int j = (chn << 5) + lane;
            bool sup = false;
            if (j < cnt && j > i) {
                float4 ob = sbox[j];
                float xx1 = fmaxf(kb.x, ob.x);
                float yy1 = fmaxf(kb.y, ob.y);
                float xx2 = fminf(kb.z, ob.z);
                float yy2 = fminf(kb.w, ob.w);
                float w = fmaxf(EPS_IOU, xx2 - xx1);
                float h = fmaxf(EPS_IOU, yy2 - yy1);
                float inter = __fmul_rn(w, h);
                float iou = inter / (ka + sarea[j] - inter);
                sup = iou > NMS_T;
            }
            unsigned m = __ballot_sync(FULLM, sup);
            if      (chn == 0) w0 = m;
            else if (chn == 1) w1 = m;
            else if (chn == 2) w2 = m;
            else               w3 = m;
        }
        if (lane == 0) rows[i] = make_uint4(w0, w1, w2, w3);
    }
    __syncthreads();

    if (tid == 0) {
        float* keep = out + (size_t)BB * NN * 6 + (size_t)b * NN;
        unsigned a0 = FULLM, a1 = FULLM, a2 = FULLM, a3 = FULLM;
        for (int k = 0; k < cnt; k++) {
            uint4 r = rows[k];
            unsigned aw = (k < 32) ? a0 : (k < 64) ? a1 : (k < 96) ? a2 : a3;
            if ((aw >> (k & 31)) & 1u) {
                keep[ssn[k]] = 1.0f;
                a0 &= ~r.x; a1 &= ~r.y; a2 &= ~r.z; a3 &= ~r.w;
            }
        }
    }
}

extern "C" void kernel_launch(void* const* d_in, const int* in_sizes, int n_in,
                              void* d_out, int out_size)
{
    const float* feat   = (const float*)d_in[0];
    const float* w_pred = (const float*)d_in[1];
    const float* b_pred = (const float*)d_in[2];
    float* out = (float*)d_out;

    k_wsplit<<<32, 512>>>(w_pred);
    k_gemm_mma<<<1024, 128>>>(feat, b_pred, out);
    k_nms<<<dim3(BB, NCLS), 128>>>(out);
}

// round 14
// speedup vs baseline: 1.2143x; 1.2143x over previous
#include <cuda_runtime.h>
#include <math.h>
#include <stdint.h>

// Problem constants
#define BB    64
#define CC    512
#define NN    1024          // 32*32 spatial
#define OO    25            // 1 conf + 20 cls + 4 box
#define OPAD  28            // pad rows to multiple of 4 for float4 smem loads
#define NCLS  20
#define CONF_T 0.01f
#define NMS_T  0.5f
#define EPS_IOU 1e-28f
#define INV_SCALE 0.0009765625f   // 1/1024
#define MAXC  128           // per-(image,class) candidate cap; mean ~51, ~11 sigma
#define FULLM 0xffffffffu
#define PF    8             // feat prefetch depth (covers ~577cyc DRAM latency)

#define NCTA  296           // exactly 2 CTAs per SM, perfectly balanced
#define PXC   222           // pixels per CTA (296*222 = 65712 >= 65536, guarded)
#define NPX   (BB*NN)

typedef unsigned long long u64;

// Compacted per-(image,class) candidate records, filled by GEMM epilogue.
// g_cnt zeroed at module load and re-zeroed by k_nms each launch -> replay-safe.
__device__ int    g_cnt [BB*NCLS];
__device__ float4 g_cbox[BB*NCLS*MAXC];
__device__ u64    g_ckey[BB*NCLS*MAXC];

__device__ __forceinline__ float sigm(float x) { return 1.0f / (1.0f + expf(-x)); }

// ---------------------------------------------------------------------------
// Decode one pixel given its 25 raw logits (bias added here). Same as R10.
// ---------------------------------------------------------------------------
__device__ __forceinline__ void decode_write(int b, int n, const float* acc,
                                             const float* b_s, float* __restrict__ out)
{
    float p[OO];
    #pragma unroll
    for (int o = 0; o < OO; o++) p[o] = acc[o] + b_s[o];

    float conf = sigm(p[0]);

    // argmax over raw class logits (== argmax of softmax), first-max tie-break
    float m = p[1]; int am = 0;
    #pragma unroll
    for (int k = 1; k < NCLS; k++)
        if (p[1 + k] > m) { m = p[1 + k]; am = k; }

    float s = 0.0f;
    #pragma unroll
    for (int k = 0; k < NCLS; k++) s += expf(p[1 + k] - m);
    float score = conf / s;          // conf * max(softmax) == conf / sum(exp(l-m))

    float gx = (float)(n & 31), gy = (float)(n >> 5);
    float cx = (sigm(p[21]) + gx) * 32.0f;
    float cy = (sigm(p[22]) + gy) * 32.0f;
    float w  = expf(p[23]);
    float h  = expf(p[24]);
    float hw = __fmul_rn(w, 0.5f);
    float hh = __fmul_rn(h, 0.5f);
    float x1 = fminf(fmaxf(__fmul_rn(cx - hw, INV_SCALE), 0.0f), 1.0f);
    float y1 = fminf(fmaxf(__fmul_rn(cy - hh, INV_SCALE), 0.0f), 1.0f);
    float x2 = fminf(fmaxf(__fmul_rn(cx + hw, INV_SCALE), 0.0f), 1.0f);
    float y2 = fminf(fmaxf(__fmul_rn(cy + hh, INV_SCALE), 0.0f), 1.0f);

    int i = b * NN + n;
    ((float4*)out)[i] = make_float4(x1, y1, x2, y2);     // boxes
    out[NPX*4 + i] = score;                              // scores
    out[NPX*5 + i] = (float)am;                          // cls_inds
    out[NPX*6 + i] = 0.0f;                               // keep default (NMS sets 1s)

    // Append compact record. Arrival order irrelevant: NMS sorts by the u64 key
    // (score desc, pixel asc), so results are deterministic.
    if (score > CONF_T) {
        int idx  = b * NCLS + am;
        int slot = atomicAdd(&g_cnt[idx], 1);
        if (slot < MAXC) {
            float off = __fmul_rn(2.0f, (float)am);
            g_cbox[idx * MAXC + slot] =
                make_float4(x1 + off, y1 + off, x2 + off, y2 + off);
            g_ckey[idx * MAXC + slot] =
                ((u64)__float_as_uint(score) << 32) | (u64)(NN - 1 - n);
        }
    }
}

#define WSMEM_WORDS (CC * OPAD)                 // 14336 words = 56 KB
#define SMEM_BYTES  ((WSMEM_WORDS + 32) * 4)

// Fused GEMM (65536 x 512 x 25) + decode.
// 296 CTAs x 128 thr, 2 px/thread -> exactly 2 CTAs per SM, balanced single wave.
// Pixel->CTA map is image-agnostic: per-thread feat offset O = b*CC*NN + n is
// cc-invariant, so CTA pixel ranges may cross image boundaries freely.
// All 512 weight rows staged once in smem; feat via 8-deep prefetch pipeline.
__global__ __launch_bounds__(128)
void k_gemm_decode(const float* __restrict__ feat,
                   const float* __restrict__ w_pred,
                   const float* __restrict__ b_pred,
                   float* __restrict__ out)
{
    extern __shared__ float smem_dyn[];
    float* w_s = smem_dyn;                      // CC x OPAD
    float* b_s = smem_dyn + WSMEM_WORDS;        // OO

    const int tid = threadIdx.x;
    const int px0 = blockIdx.x * PXC + tid;          // first pixel
    const int px1 = px0 + 128;                        // second pixel (tid < 94)
    const bool v0 = (px0 < NPX);
    const bool v1 = (tid < (PXC - 128)) && (px1 < NPX);

    const size_t O0 = v0 ? ((size_t)(px0 >> 10) * CC * NN + (px0 & (NN - 1))) : 0;
    const size_t O1 = v1 ? ((size_t)(px1 >> 10) * CC * NN + (px1 & (NN - 1))) : 0;
    const float* fp0 = feat + O0;
    const float* fp1 = feat + O1;

    // Stage all weights (padded rows; cols 25-27 zero)
    for (int i = tid; i < WSMEM_WORDS; i += 128) {
        int c = i / OPAD, o = i - c * OPAD;
        w_s[i] = (o < OO) ? w_pred[o * CC + c] : 0.0f;
    }
    if (tid < OO) b_s[tid] = b_pred[tid];
    __syncthreads();

    float acc0[OO], acc1[OO];
    #pragma unroll
    for (int o = 0; o < OO; o++) { acc0[o] = 0.0f; acc1[o] = 0.0f; }

    float buf0[PF], buf1[PF];
    #pragma unroll
    for (int k = 0; k < PF; k++) {
        buf0[k] = __ldg(fp0 + (size_t)k * NN);
        buf1[k] = __ldg(fp1 + (size_t)k * NN);
    }

    #pragma unroll 1
    for (int cc = 0; cc < CC - PF; cc += PF) {
        float cur0[PF], cur1[PF];
        #pragma unroll
        for (int k = 0; k < PF; k++) { cur0[k] = buf0[k]; cur1[k] = buf1[k]; }
        #pragma unroll
        for (int k = 0; k < PF; k++) {
            buf0[k] = __ldg(fp0 + (size_t)(cc + PF + k) * NN);
            buf1[k] = __ldg(fp1 + (size_t)(cc + PF + k) * NN);
        }
        #pragma unroll
        for (int k = 0; k < PF; k++) {
            float f0 = cur0[k], f1 = cur1[k];
            const float4* wr = (const float4*)(w_s + (cc + k) * OPAD);
            #pragma unroll
            for (int j = 0; j < 7; j++) {
                float4 w4 = wr[j];
                const int o = j * 4;
                acc0[o] = fmaf(f0, w4.x, acc0[o]);
                acc1[o] = fmaf(f1, w4.x, acc1[o]);
                if (o + 1 < OO) { acc0[o+1] = fmaf(f0, w4.y, acc0[o+1]);
                                  acc1[o+1] = fmaf(f1, w4.y, acc1[o+1]); }
                if (o + 2 < OO) { acc0[o+2] = fmaf(f0, w4.z, acc0[o+2]);
                                  acc1[o+2] = fmaf(f1, w4.z, acc1[o+2]); }
                if (o + 3 < OO) { acc0[o+3] = fmaf(f0, w4.w, acc0[o+3]);
                                  acc1[o+3] = fmaf(f1, w4.w, acc1[o+3]); }
            }
        }
    }
    #pragma unroll
    for (int k = 0; k < PF; k++) {              // epilogue: last PF channels
        float f0 = buf0[k], f1 = buf1[k];
        const float4* wr = (const float4*)(w_s + (CC - PF + k) * OPAD);
        #pragma unroll
        for (int j = 0; j < 7; j++) {
            float4 w4 = wr[j];
            const int o = j * 4;
            acc0[o] = fmaf(f0, w4.x, acc0[o]);
            acc1[o] = fmaf(f1, w4.x, acc1[o]);
            if (o + 1 < OO) { acc0[o+1] = fmaf(f0, w4.y, acc0[o+1]);
                              acc1[o+1] = fmaf(f1, w4.y, acc1[o+1]); }
            if (o + 2 < OO) { acc0[o+2] = fmaf(f0, w4.z, acc0[o+2]);
                              acc1[o+2] = fmaf(f1, w4.z, acc1[o+2]); }
            if (o + 3 < OO) { acc0[o+3] = fmaf(f0, w4.w, acc0[o+3]);
                              acc1[o+3] = fmaf(f1, w4.w, acc1[o+3]); }
        }
    }

    if (v0) decode_write(px0 >> 10, px0 & (NN - 1), acc0, b_s, out);
    if (v1) decode_write(px1 >> 10, px1 & (NN - 1), acc1, b_s, out);
}

// ---------------------------------------------------------------------------
// NMS: identical to R10 (measured 34.1us). One 128-thread block per (image,
// class); class offset 2.0 => per-class greedy == reference's global loop.
// ---------------------------------------------------------------------------
__global__ __launch_bounds__(128)
void k_nms(float* __restrict__ out)
{
    const int b    = blockIdx.x;
    const int c    = blockIdx.y;
    const int idx  = b * NCLS + c;
    const int tid  = threadIdx.x;
    const int warp = tid >> 5;
    const int lane = tid & 31;

    __shared__ int    s_cnt;
    __shared__ u64    tkey[MAXC];
    __shared__ float4 tbox[MAXC];
    __shared__ float4 sbox[MAXC];
    __shared__ float  sarea[MAXC];
    __shared__ short  ssn[MAXC];
    __shared__ uint4  rows[MAXC];

    u64    k0 = g_ckey[idx * MAXC + tid];
    float4 b0 = g_cbox[idx * MAXC + tid];
    if (tid == 0) { int ct = g_cnt[idx]; g_cnt[idx] = 0; s_cnt = min(ct, MAXC); }
    tkey[tid] = k0;
    tbox[tid] = b0;
    __syncthreads();

    const int cnt = s_cnt;
    if (cnt == 0) return;

    if (tid < cnt) {
        u64 ki = tkey[tid];
        int rank = 0;
        for (int j = 0; j < cnt; j++) rank += (tkey[j] > ki);
        float4 bx = tbox[tid];
        sbox[rank]  = bx;
        sarea[rank] = __fmul_rn(bx.z - bx.x, bx.w - bx.y);
        ssn[rank]   = (short)(NN - 1 - (int)(ki & 0xffffffffu));
    }
    __syncthreads();

    const int nch = (cnt + 31) >> 5;
    for (int i = warp; i < cnt; i += 4) {
        float4 kb = sbox[i];
        float  ka = sarea[i];
        unsigned w0 = 0, w1 = 0, w2 = 0, w3 = 0;
        for (int chn = 0; chn < nch; chn++) {
            int j = (chn << 5) + lane;
            bool sup = false;
            if (j < cnt && j > i) {
                float4 ob = sbox[j];
                float xx1 = fmaxf(kb.x, ob.x);
                float yy1 = fmaxf(kb.y, ob.y);
                float xx2 = fminf(kb.z, ob.z);
                float yy2 = fminf(kb.w, ob.w);
                float w = fmaxf(EPS_IOU, xx2 - xx1);
                float h = fmaxf(EPS_IOU, yy2 - yy1);
                float inter = __fmul_rn(w, h);
                float iou = inter / (ka + sarea[j] - inter);
                sup = iou > NMS_T;
            }
            unsigned m = __ballot_sync(FULLM, sup);
            if      (chn == 0) w0 = m;
            else if (chn == 1) w1 = m;
            else if (chn == 2) w2 = m;
            else               w3 = m;
        }
        if (lane == 0) rows[i] = make_uint4(w0, w1, w2, w3);
    }
    __syncthreads();

    if (tid == 0) {
        float* keep = out + (size_t)NPX * 6 + (size_t)b * NN;
        unsigned a0 = FULLM, a1 = FULLM, a2 = FULLM, a3 = FULLM;
        for (int k = 0; k < cnt; k++) {
            uint4 r = rows[k];
            unsigned aw = (k < 32) ? a0 : (k < 64) ? a1 : (k < 96) ? a2 : a3;
            if ((aw >> (k & 31)) & 1u) {
                keep[ssn[k]] = 1.0f;
                a0 &= ~r.x; a1 &= ~r.y; a2 &= ~r.z; a3 &= ~r.w;
            }
        }
    }
}

extern "C" void kernel_launch(void* const* d_in, const int* in_sizes, int n_in,
                              void* d_out, int out_size)
{
    const float* feat   = (const float*)d_in[0];
    const float* w_pred = (const float*)d_in[1];
    const float* b_pred = (const float*)d_in[2];
    float* out = (float*)d_out;

    static int smem_set = 0;
    if (!smem_set) {
        cudaFuncSetAttribute(k_gemm_decode,
                             cudaFuncAttributeMaxDynamicSharedMemorySize, SMEM_BYTES);
        smem_set = 1;
    }

    k_gemm_decode<<<NCTA, 128, SMEM_BYTES>>>(feat, w_pred, b_pred, out);
    k_nms<<<dim3(BB, NCLS), 128>>>(out);
}